// round 4
// baseline (speedup 1.0000x reference)
#include <cuda_runtime.h>
#include <cstdint>

// Problem constants
#define BB 8
#define CC 64
#define NN 100000
#define RR 32
#define VV (RR*RR*RR)                  // 32768 voxels
#define VOX_ELEMS ((size_t)BB*CC*VV)   // 16,777,216 floats

// ---------------- device scratch (no allocations allowed) ----------------
// Channel-contiguous sums: [B][V][C] as float4 groups -> 16B-aligned for red.v4
__device__ float4   g_scratch[(size_t)BB * VV * (CC/4)];   // 67 MB
__device__ unsigned g_count[BB * VV];                      // 1 MB
__device__ float    g_mean[BB * 3];

// ---------------- K1: fused zero-fill + per-(batch,axis) mean -------------
// Blocks 0..23: fp64 mean of coords row (b*3+axis). Blocks 24..: zero scratch.
__global__ void k_prep(const float* __restrict__ coords) {
    if (blockIdx.x < BB * 3) {
        int row = blockIdx.x;
        const float* p = coords + (size_t)row * NN;
        double s = 0.0;
        for (int i = threadIdx.x; i < NN; i += 256) s += (double)p[i];
        __shared__ double sm[256];
        sm[threadIdx.x] = s;
        __syncthreads();
        for (int off = 128; off > 0; off >>= 1) {
            if (threadIdx.x < off) sm[threadIdx.x] += sm[threadIdx.x + off];
            __syncthreads();
        }
        if (threadIdx.x == 0) g_mean[row] = (float)(sm[0] / (double)NN);
        return;
    }
    // zero-fill region: remap to dense worker id
    unsigned zblocks = gridDim.x > BB * 3 ? (gridDim.x - BB * 3) : 1u;
    size_t nworkers = (size_t)zblocks * 256;
    size_t gid = (size_t)(blockIdx.x - BB * 3) * 256 + threadIdx.x;
    const size_t n4 = (size_t)BB * VV * (CC/4);
    float4 z = make_float4(0.f, 0.f, 0.f, 0.f);
    for (size_t i = gid; i < n4; i += nworkers) g_scratch[i] = z;
    for (size_t i = gid; i < (size_t)BB * VV; i += nworkers) g_count[i] = 0u;
}

// ---------------- K2: norm coords + scatter-add (red.v4) ------------------
__device__ __forceinline__ void red_add_v4(float4* gptr, float a, float b, float c, float d) {
    asm volatile("red.global.add.v4.f32 [%0], {%1,%2,%3,%4};"
                 :: "l"(__cvta_generic_to_global(gptr)),
                    "f"(a), "f"(b), "f"(c), "f"(d)
                 : "memory");
}

__global__ void __launch_bounds__(512) k_scatter(const float* __restrict__ features,
                                                 const float* __restrict__ coords,
                                                 float* __restrict__ norm_out) {
    int gid = blockIdx.x * 512 + threadIdx.x;     // over B*N jointly
    if (gid >= BB * NN) return;
    int b = gid / NN;
    int n = gid - b * NN;

    const float* cb = coords + (size_t)b * 3 * NN;
    float x = cb[n];
    float y = cb[NN + n];
    float z = cb[2 * NN + n];

    float mx = g_mean[b*3 + 0];
    float my = g_mean[b*3 + 1];
    float mz = g_mean[b*3 + 2];

    // norm = clip(((c - mean) + 1)/2 * R, 0, R-1)  (scalings are powers of 2 -> exact)
    float sx = fminf(fmaxf((x - mx + 1.0f) * 0.5f * (float)RR, 0.0f), (float)(RR-1));
    float sy = fminf(fmaxf((y - my + 1.0f) * 0.5f * (float)RR, 0.0f), (float)(RR-1));
    float sz = fminf(fmaxf((z - mz + 1.0f) * 0.5f * (float)RR, 0.0f), (float)(RR-1));

    float* nb = norm_out + (size_t)b * 3 * NN;
    nb[n]          = sx;
    nb[NN + n]     = sy;
    nb[2 * NN + n] = sz;

    // round-half-to-even like jnp.round
    int ix = (int)rintf(sx);
    int iy = (int)rintf(sy);
    int iz = (int)rintf(sz);
    int idx = ix * (RR*RR) + iy * RR + iz;

    atomicAdd(&g_count[b * VV + idx], 1u);

    const float* fb = features + (size_t)b * CC * NN + n;
    float4* dst = &g_scratch[((size_t)b * VV + idx) * (CC/4)];
#pragma unroll
    for (int c4 = 0; c4 < CC/4; c4++) {
        float a0 = fb[(size_t)(c4*4 + 0) * NN];
        float a1 = fb[(size_t)(c4*4 + 1) * NN];
        float a2 = fb[(size_t)(c4*4 + 2) * NN];
        float a3 = fb[(size_t)(c4*4 + 3) * NN];
        red_add_v4(dst + c4, a0, a1, a2, a3);
    }
}

// ---------------- K3: divide by count + transpose [V][C] -> [C][V] --------
__global__ void k_finalize(float* __restrict__ vox_out) {
    int b  = blockIdx.y;
    int v0 = blockIdx.x * 64;
    int t  = threadIdx.x;              // 0..255

    __shared__ float tile[64 * 65];
    __shared__ float cnt[64];

    if (t < 64) {
        unsigned c = g_count[b * VV + v0 + t];
        cnt[t] = fmaxf((float)c, 1.0f);
    }

    const float* src = (const float*)g_scratch + ((size_t)b * VV + v0) * CC;
#pragma unroll
    for (int r = 0; r < 16; r++) {
        int vv = r * 4 + (t >> 6);
        int c  = t & 63;
        tile[vv * 65 + c] = src[(size_t)vv * CC + c];
    }
    __syncthreads();

    float* ob = vox_out + ((size_t)b * CC) * VV + v0;
#pragma unroll
    for (int r = 0; r < 16; r++) {
        int c  = r * 4 + (t >> 6);
        int vv = t & 63;
        ob[(size_t)c * VV + vv] = tile[vv * 65 + c] / cnt[vv];
    }
}

// ---------------- launch ---------------------------------------------------
extern "C" void kernel_launch(void* const* d_in, const int* in_sizes, int n_in,
                              void* d_out, int out_size) {
    const float* features = (const float*)d_in[0];   // [B, C, N]
    const float* coords   = (const float*)d_in[1];   // [B, 3, N]
    float* vox_out  = (float*)d_out;                 // [B, C, 32, 32, 32]
    float* norm_out = (float*)d_out + VOX_ELEMS;     // [B, 3, N]

    k_prep<<<BB * 3 + 2048, 256>>>(coords);

    int total = BB * NN;
    k_scatter<<<(total + 511) / 512, 512>>>(features, coords, norm_out);

    dim3 fg(VV / 64, BB);
    k_finalize<<<fg, 256>>>(vox_out);
}